// round 1
// baseline (speedup 1.0000x reference)
#include <cuda_runtime.h>

// Shapes (fixed per reference): B=1024, C=200, L=3, DIM=512, SEQ=C+1=201
#define B_   1024
#define C_   200
#define DIM_ 512
#define SEQ_ 201
#define BT   8        // batch rows per block iteration

// Inputs (metadata order): x [B,C] f32, W [C,3,DIM] f32, cls_token [1,1,DIM] f32, pe [SEQ,DIM] f32
// Output: [B, SEQ, DIM] f32
//
// out[b,0,d]   = cls[d] + pe[0,d]
// out[b,c+1,d] = x[b,clamp(c-1)]*W[c,0,d] + x[b,c]*W[c,1,d] + x[b,clamp(c+1)]*W[c,2,d] + pe[c+1,d]

__global__ __launch_bounds__(128, 8)
void GSE_band_proj_kernel(const float* __restrict__ x,
                          const float* __restrict__ W,
                          const float* __restrict__ cls,
                          const float* __restrict__ pe,
                          float* __restrict__ out) {
    const int s  = blockIdx.x;        // 0..200 (sequence position)
    const int d4 = threadIdx.x;       // 0..127 (float4 index into DIM=512)
    const int b_base = blockIdx.y * BT;

    if (s == 0) {
        // cls row: batch-invariant value, pure store stream
        const float4 cv = reinterpret_cast<const float4*>(cls)[d4];
        const float4 pv = reinterpret_cast<const float4*>(pe)[d4];
        float4 r;
        r.x = cv.x + pv.x;
        r.y = cv.y + pv.y;
        r.z = cv.z + pv.z;
        r.w = cv.w + pv.w;
        #pragma unroll
        for (int i = 0; i < BT; i++) {
            const size_t b = (size_t)(b_base + i);
            reinterpret_cast<float4*>(out + (b * SEQ_) * DIM_)[d4] = r;
        }
        return;
    }

    const int c   = s - 1;                       // 0..199
    const int cm1 = (c > 0)      ? c - 1 : 0;    // edge-replicate pad
    const int cp1 = (c < C_ - 1) ? c + 1 : C_ - 1;

    // Per-(c,d4) constants, loaded once, reused across BT batch rows.
    const float4 w0 = reinterpret_cast<const float4*>(W + ((size_t)c * 3 + 0) * DIM_)[d4];
    const float4 w1 = reinterpret_cast<const float4*>(W + ((size_t)c * 3 + 1) * DIM_)[d4];
    const float4 w2 = reinterpret_cast<const float4*>(W + ((size_t)c * 3 + 2) * DIM_)[d4];
    const float4 pv = reinterpret_cast<const float4*>(pe + (size_t)(c + 1) * DIM_)[d4];

    #pragma unroll
    for (int i = 0; i < BT; i++) {
        const int b = b_base + i;
        // warp-uniform scalar loads (broadcast); x is tiny and L2-resident
        const float a = __ldg(x + (size_t)b * C_ + cm1);
        const float m = __ldg(x + (size_t)b * C_ + c);
        const float z = __ldg(x + (size_t)b * C_ + cp1);

        float4 r;
        r.x = fmaf(a, w0.x, fmaf(m, w1.x, fmaf(z, w2.x, pv.x)));
        r.y = fmaf(a, w0.y, fmaf(m, w1.y, fmaf(z, w2.y, pv.y)));
        r.z = fmaf(a, w0.z, fmaf(m, w1.z, fmaf(z, w2.z, pv.z)));
        r.w = fmaf(a, w0.w, fmaf(m, w1.w, fmaf(z, w2.w, pv.w)));

        reinterpret_cast<float4*>(out + ((size_t)b * SEQ_ + s) * DIM_)[d4] = r;
    }
}

extern "C" void kernel_launch(void* const* d_in, const int* in_sizes, int n_in,
                              void* d_out, int out_size) {
    const float* x   = (const float*)d_in[0];
    const float* W   = (const float*)d_in[1];
    const float* cls = (const float*)d_in[2];
    const float* pe  = (const float*)d_in[3];
    float* out = (float*)d_out;

    dim3 grid(SEQ_, B_ / BT, 1);   // 201 x 128 blocks
    dim3 block(DIM_ / 4, 1, 1);    // 128 threads, one float4 each
    GSE_band_proj_kernel<<<grid, block>>>(x, W, cls, pe, out);
}

// round 3
// speedup vs baseline: 1.1338x; 1.1338x over previous
#include <cuda_runtime.h>

// Shapes (fixed per reference): B=1024, C=200, L=3, DIM=512, SEQ=C+1=201
#define B_   1024
#define C_   200
#define DIM_ 512
#define SEQ_ 201
#define BT   8        // batch rows per block

// out[b,0,d]   = cls[d] + pe[0,d]
// out[b,c+1,d] = x[b,clamp(c-1)]*W[c,0,d] + x[b,c]*W[c,1,d] + x[b,clamp(c+1)]*W[c,2,d] + pe[c+1,d]

__device__ __forceinline__ void stcs4(float4* p, float4 v) {
    // streaming store: evict-first in L2, drain straight to DRAM
    asm volatile("st.global.cs.v4.f32 [%0], {%1, %2, %3, %4};"
                 :: "l"(p), "f"(v.x), "f"(v.y), "f"(v.z), "f"(v.w) : "memory");
}

__global__ __launch_bounds__(128, 8)
void GSE_band_proj_kernel(const float* __restrict__ x,
                          const float* __restrict__ W,
                          const float* __restrict__ cls,
                          const float* __restrict__ pe,
                          float* __restrict__ out) {
    const int s  = blockIdx.x;        // 0..200 (sequence position)
    const int d4 = threadIdx.x;       // 0..127 (float4 index into DIM=512)
    const int b_base = blockIdx.y * BT;

    if (s == 0) {
        const float4 cv = reinterpret_cast<const float4*>(cls)[d4];
        const float4 pv = reinterpret_cast<const float4*>(pe)[d4];
        float4 r;
        r.x = cv.x + pv.x;
        r.y = cv.y + pv.y;
        r.z = cv.z + pv.z;
        r.w = cv.w + pv.w;
        #pragma unroll
        for (int i = 0; i < BT; i++) {
            const size_t b = (size_t)(b_base + i);
            stcs4(reinterpret_cast<float4*>(out + (b * SEQ_) * DIM_) + d4, r);
        }
        return;
    }

    const int c   = s - 1;                       // 0..199
    const int cm1 = (c > 0)      ? c - 1 : 0;    // edge-replicate pad
    const int cp1 = (c < C_ - 1) ? c + 1 : C_ - 1;

    // Prefetch ALL x values for the 8 batch rows first — fully independent
    // LDGs so the scoreboard overlaps them, and the store loop below never
    // waits on a load.
    float xa[BT], xm[BT], xz[BT];
    #pragma unroll
    for (int i = 0; i < BT; i++) {
        const size_t row = (size_t)(b_base + i) * C_;
        xa[i] = __ldg(x + row + cm1);
        xm[i] = __ldg(x + row + c);
        xz[i] = __ldg(x + row + cp1);
    }

    // Per-(c,d4) constants, loaded once, reused across BT batch rows.
    const float4 w0 = reinterpret_cast<const float4*>(W + ((size_t)c * 3 + 0) * DIM_)[d4];
    const float4 w1 = reinterpret_cast<const float4*>(W + ((size_t)c * 3 + 1) * DIM_)[d4];
    const float4 w2 = reinterpret_cast<const float4*>(W + ((size_t)c * 3 + 2) * DIM_)[d4];
    const float4 pv = reinterpret_cast<const float4*>(pe + (size_t)(c + 1) * DIM_)[d4];

    #pragma unroll
    for (int i = 0; i < BT; i++) {
        const size_t b = (size_t)(b_base + i);
        float4 r;
        r.x = fmaf(xa[i], w0.x, fmaf(xm[i], w1.x, fmaf(xz[i], w2.x, pv.x)));
        r.y = fmaf(xa[i], w0.y, fmaf(xm[i], w1.y, fmaf(xz[i], w2.y, pv.y)));
        r.z = fmaf(xa[i], w0.z, fmaf(xm[i], w1.z, fmaf(xz[i], w2.z, pv.z)));
        r.w = fmaf(xa[i], w0.w, fmaf(xm[i], w1.w, fmaf(xz[i], w2.w, pv.w)));
        stcs4(reinterpret_cast<float4*>(out + (b * SEQ_ + s) * DIM_) + d4, r);
    }
}

extern "C" void kernel_launch(void* const* d_in, const int* in_sizes, int n_in,
                              void* d_out, int out_size) {
    const float* x   = (const float*)d_in[0];
    const float* W   = (const float*)d_in[1];
    const float* cls = (const float*)d_in[2];
    const float* pe  = (const float*)d_in[3];
    float* out = (float*)d_out;

    dim3 grid(SEQ_, B_ / BT, 1);   // 201 x 128 blocks
    dim3 block(DIM_ / 4, 1, 1);    // 128 threads, one float4 each
    GSE_band_proj_kernel<<<grid, block>>>(x, W, cls, pe, out);
}